// round 2
// baseline (speedup 1.0000x reference)
#include <cuda_runtime.h>
#include <math.h>

#define TT 512
#define BB 64
#define CC 256
#define HH 1024
#define RR (TT*BB)

#define WPAD 36
#define NB_RNN 128
#define RNN_SMEM ((1024*WPAD + 1024*16)*4)   // 212992 bytes

// ---------------- scratch ----------------
__device__ float g_xw[(size_t)TT*BB*HH];
__device__ float g_y0[(size_t)TT*BB*HH];
__device__ float g_y1[(size_t)TT*BB*HH];

// ---------------- grid barrier ----------------
__device__ unsigned g_cnt = 0;
__device__ volatile unsigned g_gen = 0;

__device__ __forceinline__ void grid_sync(unsigned nb) {
    __syncthreads();
    if (threadIdx.x == 0) {
        unsigned my = g_gen;
        __threadfence();
        if (atomicAdd(&g_cnt, 1u) == nb - 1u) {
            g_cnt = 0u;
            __threadfence();
            g_gen = my + 1u;
        } else {
            while (g_gen == my) { __nanosleep(32); }
        }
        __threadfence();
    }
    __syncthreads();
}

// ---------------- parallel GEMM: out[R,N] = A[R,K] @ W[N,K]^T + b1(+b2) ----
__global__ __launch_bounds__(256) void gemm_bias_kernel(
    const float* __restrict__ A, const float* __restrict__ W,
    const float* __restrict__ b1, const float* __restrict__ b2,
    float* __restrict__ out, int R, int N, int K)
{
    __shared__ float As[16][132];
    __shared__ float Ws[16][132];
    const int tid  = threadIdx.x;
    const int r0   = blockIdx.y * 128;
    const int c0   = blockIdx.x * 128;
    const int lr   = tid >> 1;
    const int lq   = (tid & 1) * 4;
    const int lane = tid & 31;
    const int w    = tid >> 5;
    const int tx = ((w & 1) << 3) + (lane & 7);
    const int ty = ((w >> 1) << 2) + (lane >> 3);

    float acc[8][8];
    #pragma unroll
    for (int i = 0; i < 8; i++)
        #pragma unroll
        for (int j = 0; j < 8; j++) acc[i][j] = 0.f;

    const float* Arow = A + (size_t)(r0 + lr) * K;
    const float* Wrow = W + (size_t)(c0 + lr) * K;

    for (int k0 = 0; k0 < K; k0 += 16) {
        #pragma unroll
        for (int l = 0; l < 2; l++) {
            float4 av = *(const float4*)(Arow + k0 + l*8 + lq);
            float4 wv = *(const float4*)(Wrow + k0 + l*8 + lq);
            int kk = l*8 + lq;
            As[kk+0][lr] = av.x;  As[kk+1][lr] = av.y;
            As[kk+2][lr] = av.z;  As[kk+3][lr] = av.w;
            Ws[kk+0][lr] = wv.x;  Ws[kk+1][lr] = wv.y;
            Ws[kk+2][lr] = wv.z;  Ws[kk+3][lr] = wv.w;
        }
        __syncthreads();
        #pragma unroll
        for (int kk = 0; kk < 16; kk++) {
            float4 a0 = *(const float4*)&As[kk][ty*8];
            float4 a1 = *(const float4*)&As[kk][ty*8+4];
            float4 w0 = *(const float4*)&Ws[kk][tx*8];
            float4 w1 = *(const float4*)&Ws[kk][tx*8+4];
            float ar[8] = {a0.x,a0.y,a0.z,a0.w,a1.x,a1.y,a1.z,a1.w};
            float wr[8] = {w0.x,w0.y,w0.z,w0.w,w1.x,w1.y,w1.z,w1.w};
            #pragma unroll
            for (int i = 0; i < 8; i++)
                #pragma unroll
                for (int j = 0; j < 8; j++)
                    acc[i][j] += ar[i] * wr[j];
        }
        __syncthreads();
    }

    float bias[8];
    #pragma unroll
    for (int j = 0; j < 8; j++) {
        int col = c0 + tx*8 + j;
        bias[j] = b1[col] + (b2 ? b2[col] : 0.f);
    }
    #pragma unroll
    for (int i = 0; i < 8; i++) {
        int row = r0 + ty*8 + i;
        float4 v0 = make_float4(acc[i][0]+bias[0], acc[i][1]+bias[1],
                                acc[i][2]+bias[2], acc[i][3]+bias[3]);
        float4 v1 = make_float4(acc[i][4]+bias[4], acc[i][5]+bias[5],
                                acc[i][6]+bias[6], acc[i][7]+bias[7]);
        *(float4*)(out + (size_t)row*N + c0 + tx*8)     = v0;
        *(float4*)(out + (size_t)row*N + c0 + tx*8 + 4) = v1;
    }
}

// ------------- persistent recurrence: y[t]=tanh(xw[t]+h_{t-1}@Whh^T) -------
// 128 CTAs = 4 batch-groups(16) x 32 col-groups(32). Whh slice resident smem.
__global__ __launch_bounds__(256) void rnn_layer_kernel(
    const float* __restrict__ xw, const float* __restrict__ h0,
    const float* __restrict__ Whh, float* __restrict__ y, int nsteps)
{
    extern __shared__ float smem[];
    float* Wsh = smem;                 // [1024][WPAD] transposed W slice
    float* hsm = smem + 1024*WPAD;     // [1024][16] transposed h; reused for reduce

    const int tid = threadIdx.x;
    const int bid = blockIdx.x;
    const int cg  = bid & 31;
    const int bg  = bid >> 5;
    const int c0  = cg * 32;

    // one-time W slice load, transposed: Wsh[k][j_local]
    {
        const int j  = tid & 31;
        const int kc = tid >> 5;       // 0..7, each 128 k
        const float* wr = Whh + (size_t)(c0 + j) * HH + kc*128;
        #pragma unroll
        for (int i = 0; i < 32; i++) {
            float4 v = *(const float4*)(wr + i*4);
            int k = kc*128 + i*4;
            Wsh[(k+0)*WPAD + j] = v.x;
            Wsh[(k+1)*WPAD + j] = v.y;
            Wsh[(k+2)*WPAD + j] = v.z;
            Wsh[(k+3)*WPAD + j] = v.w;
        }
    }

    const int hb   = tid & 15;
    const int hkc  = tid >> 4;         // 0..15, each 64 k
    const int tile = tid & 15;
    const int kg   = tid >> 4;         // 16-way K split
    const int bl0  = (tile >> 2) * 4;
    const int jl0  = (tile & 3) * 8;

    for (int t = 0; t < nsteps; t++) {
        const float* hprev = (t == 0) ? h0 : (y + (size_t)(t-1)*BB*HH);
        __syncthreads();  // W-load done (t=0); reduce-buffer free for reuse

        // load h tile transposed: hsm[k][b_local]
        {
            const float* hr = hprev + (size_t)(bg*16 + hb)*HH + hkc*64;
            #pragma unroll
            for (int i = 0; i < 16; i++) {
                float4 v = *(const float4*)(hr + i*4);
                int k = hkc*64 + i*4;
                hsm[(k+0)*16 + hb] = v.x;
                hsm[(k+1)*16 + hb] = v.y;
                hsm[(k+2)*16 + hb] = v.z;
                hsm[(k+3)*16 + hb] = v.w;
            }
        }
        __syncthreads();

        float acc[4][8];
        #pragma unroll
        for (int r = 0; r < 4; r++)
            #pragma unroll
            for (int c = 0; c < 8; c++) acc[r][c] = 0.f;

        #pragma unroll 8
        for (int i = 0; i < 64; i++) {
            int k = i*16 + kg;
            float4 hv = *(const float4*)&hsm[k*16 + bl0];
            float4 w0 = *(const float4*)&Wsh[k*WPAD + jl0];
            float4 w1 = *(const float4*)&Wsh[k*WPAD + jl0 + 4];
            float hr4[4] = {hv.x, hv.y, hv.z, hv.w};
            float wr8[8] = {w0.x,w0.y,w0.z,w0.w,w1.x,w1.y,w1.z,w1.w};
            #pragma unroll
            for (int r = 0; r < 4; r++)
                #pragma unroll
                for (int c = 0; c < 8; c++)
                    acc[r][c] += hr4[r] * wr8[c];
        }
        __syncthreads();

        // cross-kg reduction via smem (reuse hsm region; 16*513 < 16384 floats)
        float* red = hsm;
        #pragma unroll
        for (int r = 0; r < 4; r++)
            #pragma unroll
            for (int c = 0; c < 8; c++)
                red[kg*513 + (bl0+r)*32 + jl0 + c] = acc[r][c];
        __syncthreads();

        #pragma unroll
        for (int o = tid; o < 512; o += 256) {
            float s = 0.f;
            #pragma unroll
            for (int g = 0; g < 16; g++) s += red[g*513 + o];
            int bbq = bg*16 + (o >> 5);
            int jj  = c0 + (o & 31);
            size_t idx = ((size_t)t*BB + bbq)*HH + jj;
            y[idx] = tanhf(xw[idx] + s);
        }

        __threadfence();
        grid_sync(NB_RNN);
    }
}

// ------------- hidden-state gather: out_hidden[l,b,h] = y_l[T-1,b,h] --------
__global__ void gather_hidden_kernel(float* __restrict__ out_hidden)
{
    int i = blockIdx.x * blockDim.x + threadIdx.x;   // 0 .. 2*B*H-1
    const float* src = (i < BB*HH)
        ? (g_y0 + (size_t)(TT-1)*BB*HH + i)
        : (g_y1 + (size_t)(TT-1)*BB*HH + (i - BB*HH));
    out_hidden[i] = *src;
}

extern "C" void kernel_launch(void* const* d_in, const int* in_sizes, int n_in,
                              void* d_out, int out_size) {
    const float* x     = (const float*)d_in[0];
    const float* h0    = (const float*)d_in[1];
    const float* w_ih0 = (const float*)d_in[2];
    const float* w_hh0 = (const float*)d_in[3];
    const float* b_ih0 = (const float*)d_in[4];
    const float* b_hh0 = (const float*)d_in[5];
    const float* w_ih1 = (const float*)d_in[6];
    const float* w_hh1 = (const float*)d_in[7];
    const float* b_ih1 = (const float*)d_in[8];
    const float* b_hh1 = (const float*)d_in[9];
    const float* w_dec = (const float*)d_in[10];
    const float* b_dec = (const float*)d_in[11];
    float* out = (float*)d_out;

    static int configured = 0;
    if (!configured) {
        cudaFuncSetAttribute(rnn_layer_kernel,
                             cudaFuncAttributeMaxDynamicSharedMemorySize, RNN_SMEM);
        configured = 1;
    }

    float* xw;  cudaGetSymbolAddress((void**)&xw,  g_xw);
    float* y0;  cudaGetSymbolAddress((void**)&y0,  g_y0);
    float* y1;  cudaGetSymbolAddress((void**)&y1,  g_y1);

    dim3 blk(256);

    // 1) layer-0 input projection: xw = x @ w_ih0^T + b_ih0 + b_hh0
    {
        dim3 grid(HH/128, RR/128);
        gemm_bias_kernel<<<grid, blk>>>(x, w_ih0, b_ih0, b_hh0, xw, RR, HH, CC);
    }
    // 2) layer-0 recurrence
    rnn_layer_kernel<<<NB_RNN, blk, RNN_SMEM>>>(xw, h0, w_hh0, y0, TT);
    // 3) layer-1 input projection: xw = y0 @ w_ih1^T + b_ih1 + b_hh1
    {
        dim3 grid(HH/128, RR/128);
        gemm_bias_kernel<<<grid, blk>>>(y0, w_ih1, b_ih1, b_hh1, xw, RR, HH, HH);
    }
    // 4) layer-1 recurrence
    rnn_layer_kernel<<<NB_RNN, blk, RNN_SMEM>>>(xw, h0 + BB*HH, w_hh1, y1, TT);
    // 5) decoder: out[:TBC] = y1 @ w_dec^T + b_dec
    {
        dim3 grid(CC/128, RR/128);
        gemm_bias_kernel<<<grid, blk>>>(y1, w_dec, b_dec, nullptr, out, RR, CC, HH);
    }
    // 6) hidden states appended after decoded
    gather_hidden_kernel<<<(2*BB*HH)/256, blk>>>(out + (size_t)TT*BB*CC);
}

// round 3
// speedup vs baseline: 1.0925x; 1.0925x over previous
#include <cuda_runtime.h>
#include <math.h>

#define TT 512
#define BB 64
#define CC 256
#define HH 1024
#define RR (TT*BB)

#define WPAD 36
#define NB_RNN 128
// W slice 1024x36 floats + reduction buffer 32*258 ull
#define RED_ULL_STRIDE 258
#define RNN_SMEM (1024*WPAD*4 + 32*RED_ULL_STRIDE*8)   // 147456 + 66048 = 213504

typedef unsigned long long ull;

// ---------------- packed fp32x2 helpers ----------------
#define PACKDUP(d, s) asm("mov.b64 %0, {%1, %1};" : "=l"(d) : "r"(__float_as_uint(s)))
#define FFMA2(acc, a, b) asm("fma.rn.f32x2 %0, %1, %2, %0;" : "+l"(acc) : "l"(a), "l"(b))
#define ADD2(d, a, b) asm("add.rn.f32x2 %0, %1, %2;" : "=l"(d) : "l"(a), "l"(b))
#define UNPACK2(lo, hi, v) asm("mov.b64 {%0, %1}, %2;" : "=r"(lo), "=r"(hi) : "l"(v))

// ---------------- scratch ----------------
__device__ float g_xw[(size_t)TT*BB*HH];
__device__ float g_y0[(size_t)TT*BB*HH];
__device__ float g_y1[(size_t)TT*BB*HH];

// ---------------- grid barrier (release/acquire scoped atomics) ------------
__device__ unsigned g_cnt = 0;
__device__ unsigned g_gen = 0;

__device__ __forceinline__ void grid_sync(unsigned nb) {
    __syncthreads();
    if (threadIdx.x == 0) {
        unsigned my;
        asm volatile("ld.relaxed.gpu.global.u32 %0, [%1];"
                     : "=r"(my) : "l"(&g_gen) : "memory");
        unsigned old;
        asm volatile("atom.release.gpu.global.add.u32 %0, [%1], 1;"
                     : "=r"(old) : "l"(&g_cnt) : "memory");
        if (old == nb - 1u) {
            asm volatile("st.relaxed.gpu.global.u32 [%0], %1;"
                         :: "l"(&g_cnt), "r"(0u) : "memory");
            asm volatile("st.release.gpu.global.u32 [%0], %1;"
                         :: "l"(&g_gen), "r"(my + 1u) : "memory");
        } else {
            unsigned v;
            do {
                asm volatile("ld.acquire.gpu.global.u32 %0, [%1];"
                             : "=r"(v) : "l"(&g_gen) : "memory");
            } while (v == my);
        }
    }
    __syncthreads();
}

// ---------------- parallel GEMM: out[R,N] = A[R,K] @ W[N,K]^T + b1(+b2) ----
__global__ __launch_bounds__(256) void gemm_bias_kernel(
    const float* __restrict__ A, const float* __restrict__ W,
    const float* __restrict__ b1, const float* __restrict__ b2,
    float* __restrict__ out, int R, int N, int K)
{
    __shared__ float As[16][132];
    __shared__ float Ws[16][132];
    const int tid  = threadIdx.x;
    const int r0   = blockIdx.y * 128;
    const int c0   = blockIdx.x * 128;
    const int lr   = tid >> 1;
    const int lq   = (tid & 1) * 4;
    const int lane = tid & 31;
    const int w    = tid >> 5;
    const int tx = ((w & 1) << 3) + (lane & 7);
    const int ty = ((w >> 1) << 2) + (lane >> 3);

    ull acc2[8][4];
    #pragma unroll
    for (int i = 0; i < 8; i++)
        #pragma unroll
        for (int c = 0; c < 4; c++) acc2[i][c] = 0ull;

    const float* Arow = A + (size_t)(r0 + lr) * K;
    const float* Wrow = W + (size_t)(c0 + lr) * K;

    for (int k0 = 0; k0 < K; k0 += 16) {
        #pragma unroll
        for (int l = 0; l < 2; l++) {
            float4 av = *(const float4*)(Arow + k0 + l*8 + lq);
            float4 wv = *(const float4*)(Wrow + k0 + l*8 + lq);
            int kk = l*8 + lq;
            As[kk+0][lr] = av.x;  As[kk+1][lr] = av.y;
            As[kk+2][lr] = av.z;  As[kk+3][lr] = av.w;
            Ws[kk+0][lr] = wv.x;  Ws[kk+1][lr] = wv.y;
            Ws[kk+2][lr] = wv.z;  Ws[kk+3][lr] = wv.w;
        }
        __syncthreads();
        #pragma unroll
        for (int kk = 0; kk < 16; kk++) {
            float4 a0 = *(const float4*)&As[kk][ty*8];
            float4 a1 = *(const float4*)&As[kk][ty*8+4];
            ulonglong2 wv0 = *(const ulonglong2*)&Ws[kk][tx*8];
            ulonglong2 wv1 = *(const ulonglong2*)&Ws[kk][tx*8+4];
            ull wp0 = wv0.x, wp1 = wv0.y, wp2 = wv1.x, wp3 = wv1.y;
            float av8[8] = {a0.x,a0.y,a0.z,a0.w,a1.x,a1.y,a1.z,a1.w};
            #pragma unroll
            for (int i = 0; i < 8; i++) {
                ull ad; PACKDUP(ad, av8[i]);
                FFMA2(acc2[i][0], ad, wp0);
                FFMA2(acc2[i][1], ad, wp1);
                FFMA2(acc2[i][2], ad, wp2);
                FFMA2(acc2[i][3], ad, wp3);
            }
        }
        __syncthreads();
    }

    float bias[8];
    #pragma unroll
    for (int j = 0; j < 8; j++) {
        int col = c0 + tx*8 + j;
        bias[j] = b1[col] + (b2 ? b2[col] : 0.f);
    }
    #pragma unroll
    for (int i = 0; i < 8; i++) {
        float o[8];
        #pragma unroll
        for (int c = 0; c < 4; c++) {
            unsigned lo, hi;
            UNPACK2(lo, hi, acc2[i][c]);
            o[2*c]   = __uint_as_float(lo) + bias[2*c];
            o[2*c+1] = __uint_as_float(hi) + bias[2*c+1];
        }
        int row = r0 + ty*8 + i;
        *(float4*)(out + (size_t)row*N + c0 + tx*8)     = make_float4(o[0],o[1],o[2],o[3]);
        *(float4*)(out + (size_t)row*N + c0 + tx*8 + 4) = make_float4(o[4],o[5],o[6],o[7]);
    }
}

// ------------- persistent recurrence: y[t]=tanh(xw[t]+h_{t-1}@Whh^T) -------
// 128 CTAs = 4 batch-groups(16) x 32 col-groups(32). Whh slice resident smem.
// 8 thread-tiles of 8b x 8j, 32-way K split, f32x2 FMAs.
__global__ __launch_bounds__(256) void rnn_layer_kernel(
    const float* __restrict__ xw, const float* __restrict__ h0,
    const float* __restrict__ Whh, float* __restrict__ y, int nsteps)
{
    extern __shared__ float smem[];
    float* Wsh = smem;                 // [1024][WPAD] transposed W slice
    float* hsm = smem + 1024*WPAD;     // [1024][16] transposed h; reused for reduce
    ull*   red2 = (ull*)hsm;

    const int tid = threadIdx.x;
    const int bid = blockIdx.x;
    const int cg  = bid & 31;
    const int bg  = bid >> 5;
    const int c0  = cg * 32;

    // one-time W slice load, transposed: Wsh[k][j_local]
    {
        const int j  = tid & 31;
        const int kc = tid >> 5;       // 0..7, each 128 k
        const float* wr = Whh + (size_t)(c0 + j) * HH + kc*128;
        #pragma unroll
        for (int i = 0; i < 32; i++) {
            float4 v = *(const float4*)(wr + i*4);
            int k = kc*128 + i*4;
            Wsh[(k+0)*WPAD + j] = v.x;
            Wsh[(k+1)*WPAD + j] = v.y;
            Wsh[(k+2)*WPAD + j] = v.z;
            Wsh[(k+3)*WPAD + j] = v.w;
        }
    }

    const int hb   = tid & 15;
    const int hkc  = tid >> 4;         // 0..15, each 64 k
    const int tile = tid & 7;          // 8 tiles: 2(b) x 4(j)
    const int kg   = tid >> 3;         // 32-way K split
    const int bl0  = (tile >> 2) * 8;  // 0 or 8
    const int jl0  = (tile & 3) * 8;   // 0,8,16,24

    for (int t = 0; t < nsteps; t++) {
        const float* hprev = (t == 0) ? h0 : (y + (size_t)(t-1)*BB*HH);
        __syncthreads();  // W-load done (t=0); red buffer free for reuse

        // load h tile transposed: hsm[k][b_local]
        {
            const float* hr = hprev + (size_t)(bg*16 + hb)*HH + hkc*64;
            #pragma unroll
            for (int i = 0; i < 16; i++) {
                float4 v = *(const float4*)(hr + i*4);
                int k = hkc*64 + i*4;
                hsm[(k+0)*16 + hb] = v.x;
                hsm[(k+1)*16 + hb] = v.y;
                hsm[(k+2)*16 + hb] = v.z;
                hsm[(k+3)*16 + hb] = v.w;
            }
        }
        __syncthreads();

        ull acc2[8][4];
        #pragma unroll
        for (int r = 0; r < 8; r++)
            #pragma unroll
            for (int c = 0; c < 4; c++) acc2[r][c] = 0ull;

        #pragma unroll 2
        for (int i = 0; i < 32; i++) {
            int k = i*32 + kg;
            float4 h0v = *(const float4*)&hsm[k*16 + bl0];
            float4 h1v = *(const float4*)&hsm[k*16 + bl0 + 4];
            ulonglong2 wv0 = *(const ulonglong2*)&Wsh[k*WPAD + jl0];
            ulonglong2 wv1 = *(const ulonglong2*)&Wsh[k*WPAD + jl0 + 4];
            ull wp0 = wv0.x, wp1 = wv0.y, wp2 = wv1.x, wp3 = wv1.y;
            float hv[8] = {h0v.x,h0v.y,h0v.z,h0v.w,h1v.x,h1v.y,h1v.z,h1v.w};
            #pragma unroll
            for (int r = 0; r < 8; r++) {
                ull hd; PACKDUP(hd, hv[r]);
                FFMA2(acc2[r][0], hd, wp0);
                FFMA2(acc2[r][1], hd, wp1);
                FFMA2(acc2[r][2], hd, wp2);
                FFMA2(acc2[r][3], hd, wp3);
            }
        }
        __syncthreads();   // done reading hsm; safe to overwrite as red buffer

        // write partials: pair index = (b)*16 + j/2
        #pragma unroll
        for (int r = 0; r < 8; r++)
            #pragma unroll
            for (int c = 0; c < 4; c++) {
                int p = (bl0 + r) * 16 + (jl0 >> 1) + c;
                red2[kg*RED_ULL_STRIDE + p] = acc2[r][c];
            }
        __syncthreads();

        // reduce 32 partials; each thread owns one output pair p = tid
        {
            ull s0 = red2[tid];
            ull s1 = red2[RED_ULL_STRIDE + tid];
            ull s2 = red2[2*RED_ULL_STRIDE + tid];
            ull s3 = red2[3*RED_ULL_STRIDE + tid];
            #pragma unroll
            for (int g = 4; g < 32; g += 4) {
                ADD2(s0, s0, red2[(g+0)*RED_ULL_STRIDE + tid]);
                ADD2(s1, s1, red2[(g+1)*RED_ULL_STRIDE + tid]);
                ADD2(s2, s2, red2[(g+2)*RED_ULL_STRIDE + tid]);
                ADD2(s3, s3, red2[(g+3)*RED_ULL_STRIDE + tid]);
            }
            ADD2(s0, s0, s1);
            ADD2(s2, s2, s3);
            ADD2(s0, s0, s2);
            unsigned lo, hi;
            UNPACK2(lo, hi, s0);
            int b_local = tid >> 4;
            int j = (tid & 15) * 2;
            int bq = bg*16 + b_local;
            size_t idx = ((size_t)t*BB + bq)*HH + c0 + j;
            float2 xwv = *(const float2*)&xw[idx];
            float2 rv;
            rv.x = tanhf(xwv.x + __uint_as_float(lo));
            rv.y = tanhf(xwv.y + __uint_as_float(hi));
            *(float2*)&y[idx] = rv;
        }

        grid_sync(NB_RNN);
    }
}

// ------------- hidden-state gather ----------------
__global__ void gather_hidden_kernel(float* __restrict__ out_hidden)
{
    int i = blockIdx.x * blockDim.x + threadIdx.x;
    const float* src = (i < BB*HH)
        ? (g_y0 + (size_t)(TT-1)*BB*HH + i)
        : (g_y1 + (size_t)(TT-1)*BB*HH + (i - BB*HH));
    out_hidden[i] = *src;
}

extern "C" void kernel_launch(void* const* d_in, const int* in_sizes, int n_in,
                              void* d_out, int out_size) {
    const float* x     = (const float*)d_in[0];
    const float* h0    = (const float*)d_in[1];
    const float* w_ih0 = (const float*)d_in[2];
    const float* w_hh0 = (const float*)d_in[3];
    const float* b_ih0 = (const float*)d_in[4];
    const float* b_hh0 = (const float*)d_in[5];
    const float* w_ih1 = (const float*)d_in[6];
    const float* w_hh1 = (const float*)d_in[7];
    const float* b_ih1 = (const float*)d_in[8];
    const float* b_hh1 = (const float*)d_in[9];
    const float* w_dec = (const float*)d_in[10];
    const float* b_dec = (const float*)d_in[11];
    float* out = (float*)d_out;

    cudaFuncSetAttribute(rnn_layer_kernel,
                         cudaFuncAttributeMaxDynamicSharedMemorySize, RNN_SMEM);

    float* xw;  cudaGetSymbolAddress((void**)&xw,  g_xw);
    float* y0;  cudaGetSymbolAddress((void**)&y0,  g_y0);
    float* y1;  cudaGetSymbolAddress((void**)&y1,  g_y1);

    dim3 blk(256);

    // 1) layer-0 input projection: xw = x @ w_ih0^T + b_ih0 + b_hh0
    {
        dim3 grid(HH/128, RR/128);
        gemm_bias_kernel<<<grid, blk>>>(x, w_ih0, b_ih0, b_hh0, xw, RR, HH, CC);
    }
    // 2) layer-0 recurrence
    rnn_layer_kernel<<<NB_RNN, blk, RNN_SMEM>>>(xw, h0, w_hh0, y0, TT);
    // 3) layer-1 input projection
    {
        dim3 grid(HH/128, RR/128);
        gemm_bias_kernel<<<grid, blk>>>(y0, w_ih1, b_ih1, b_hh1, xw, RR, HH, HH);
    }
    // 4) layer-1 recurrence
    rnn_layer_kernel<<<NB_RNN, blk, RNN_SMEM>>>(xw, h0 + BB*HH, w_hh1, y1, TT);
    // 5) decoder
    {
        dim3 grid(CC/128, RR/128);
        gemm_bias_kernel<<<grid, blk>>>(y1, w_dec, b_dec, nullptr, out, RR, CC, HH);
    }
    // 6) hidden states appended after decoded
    gather_hidden_kernel<<<(2*BB*HH)/256, blk>>>(out + (size_t)TT*BB*CC);
}

// round 4
// speedup vs baseline: 1.0949x; 1.0022x over previous
#include <cuda_runtime.h>
#include <math.h>

#define TT 512
#define BB 64
#define CC 256
#define HH 1024
#define RR (TT*BB)

#define WPAD 36
#define NB_RNN 128
// W slice 1024x36 floats + reduction buffer 32*258 ull
#define RED_ULL_STRIDE 258
#define RNN_SMEM (1024*WPAD*4 + 32*RED_ULL_STRIDE*8)   // 147456 + 66048 = 213504

typedef unsigned long long ull;

// ---------------- packed fp32x2 helpers ----------------
#define PACKDUP(d, s) asm("mov.b64 %0, {%1, %1};" : "=l"(d) : "r"(__float_as_uint(s)))
#define FFMA2(acc, a, b) asm("fma.rn.f32x2 %0, %1, %2, %0;" : "+l"(acc) : "l"(a), "l"(b))
#define ADD2(d, a, b) asm("add.rn.f32x2 %0, %1, %2;" : "=l"(d) : "l"(a), "l"(b))
#define UNPACK2(lo, hi, v) asm("mov.b64 {%0, %1}, %2;" : "=r"(lo), "=r"(hi) : "l"(v))

// ---------------- scratch ----------------
__device__ float g_xw[(size_t)TT*BB*HH];
__device__ float g_y0[(size_t)TT*BB*HH];
__device__ float g_y1[(size_t)TT*BB*HH];

// ---------------- grid barrier (release/acquire scoped atomics) ------------
__device__ unsigned g_cnt = 0;
__device__ unsigned g_gen = 0;

__device__ __forceinline__ void grid_sync(unsigned nb) {
    __syncthreads();
    if (threadIdx.x == 0) {
        unsigned my;
        asm volatile("ld.relaxed.gpu.global.u32 %0, [%1];"
                     : "=r"(my) : "l"(&g_gen) : "memory");
        unsigned old;
        asm volatile("atom.release.gpu.global.add.u32 %0, [%1], 1;"
                     : "=r"(old) : "l"(&g_cnt) : "memory");
        if (old == nb - 1u) {
            asm volatile("st.relaxed.gpu.global.u32 [%0], %1;"
                         :: "l"(&g_cnt), "r"(0u) : "memory");
            asm volatile("st.release.gpu.global.u32 [%0], %1;"
                         :: "l"(&g_gen), "r"(my + 1u) : "memory");
        } else {
            unsigned v;
            do {
                asm volatile("ld.acquire.gpu.global.u32 %0, [%1];"
                             : "=r"(v) : "l"(&g_gen) : "memory");
            } while (v == my);
        }
    }
    __syncthreads();
}

// ---------------- parallel GEMM: out[R,N] = A[R,K] @ W[N,K]^T + b1(+b2) ----
__global__ __launch_bounds__(256) void gemm_bias_kernel(
    const float* __restrict__ A, const float* __restrict__ W,
    const float* __restrict__ b1, const float* __restrict__ b2,
    float* __restrict__ out, int R, int N, int K)
{
    __shared__ float As[16][132];
    __shared__ float Ws[16][132];
    const int tid  = threadIdx.x;
    const int r0   = blockIdx.y * 128;
    const int c0   = blockIdx.x * 128;
    const int lr   = tid >> 1;
    const int lq   = (tid & 1) * 4;
    const int lane = tid & 31;
    const int w    = tid >> 5;
    const int tx = ((w & 1) << 3) + (lane & 7);
    const int ty = ((w >> 1) << 2) + (lane >> 3);

    ull acc2[8][4];
    #pragma unroll
    for (int i = 0; i < 8; i++)
        #pragma unroll
        for (int c = 0; c < 4; c++) acc2[i][c] = 0ull;

    const float* Arow = A + (size_t)(r0 + lr) * K;
    const float* Wrow = W + (size_t)(c0 + lr) * K;

    for (int k0 = 0; k0 < K; k0 += 16) {
        #pragma unroll
        for (int l = 0; l < 2; l++) {
            float4 av = *(const float4*)(Arow + k0 + l*8 + lq);
            float4 wv = *(const float4*)(Wrow + k0 + l*8 + lq);
            int kk = l*8 + lq;
            As[kk+0][lr] = av.x;  As[kk+1][lr] = av.y;
            As[kk+2][lr] = av.z;  As[kk+3][lr] = av.w;
            Ws[kk+0][lr] = wv.x;  Ws[kk+1][lr] = wv.y;
            Ws[kk+2][lr] = wv.z;  Ws[kk+3][lr] = wv.w;
        }
        __syncthreads();
        #pragma unroll
        for (int kk = 0; kk < 16; kk++) {
            float4 a0 = *(const float4*)&As[kk][ty*8];
            float4 a1 = *(const float4*)&As[kk][ty*8+4];
            ulonglong2 wv0 = *(const ulonglong2*)&Ws[kk][tx*8];
            ulonglong2 wv1 = *(const ulonglong2*)&Ws[kk][tx*8+4];
            ull wp0 = wv0.x, wp1 = wv0.y, wp2 = wv1.x, wp3 = wv1.y;
            float av8[8] = {a0.x,a0.y,a0.z,a0.w,a1.x,a1.y,a1.z,a1.w};
            #pragma unroll
            for (int i = 0; i < 8; i++) {
                ull ad; PACKDUP(ad, av8[i]);
                FFMA2(acc2[i][0], ad, wp0);
                FFMA2(acc2[i][1], ad, wp1);
                FFMA2(acc2[i][2], ad, wp2);
                FFMA2(acc2[i][3], ad, wp3);
            }
        }
        __syncthreads();
    }

    float bias[8];
    #pragma unroll
    for (int j = 0; j < 8; j++) {
        int col = c0 + tx*8 + j;
        bias[j] = b1[col] + (b2 ? b2[col] : 0.f);
    }
    #pragma unroll
    for (int i = 0; i < 8; i++) {
        float o[8];
        #pragma unroll
        for (int c = 0; c < 4; c++) {
            unsigned lo, hi;
            UNPACK2(lo, hi, acc2[i][c]);
            o[2*c]   = __uint_as_float(lo) + bias[2*c];
            o[2*c+1] = __uint_as_float(hi) + bias[2*c+1];
        }
        int row = r0 + ty*8 + i;
        *(float4*)(out + (size_t)row*N + c0 + tx*8)     = make_float4(o[0],o[1],o[2],o[3]);
        *(float4*)(out + (size_t)row*N + c0 + tx*8 + 4) = make_float4(o[4],o[5],o[6],o[7]);
    }
}

// ------------- persistent recurrence: y[t]=tanh(xw[t]+h_{t-1}@Whh^T) -------
// 128 CTAs = 4 batch-groups(16) x 32 col-groups(32). Whh slice resident smem.
// 8 thread-tiles of 8b x 8j, 32-way K split, f32x2 FMAs.
__global__ __launch_bounds__(256) void rnn_layer_kernel(
    const float* __restrict__ xw, const float* __restrict__ h0,
    const float* __restrict__ Whh, float* __restrict__ y, int nsteps)
{
    extern __shared__ float smem[];
    float* Wsh = smem;                 // [1024][WPAD] transposed W slice
    float* hsm = smem + 1024*WPAD;     // [1024][16] transposed h; reused for reduce
    ull*   red2 = (ull*)hsm;

    const int tid = threadIdx.x;
    const int bid = blockIdx.x;
    const int cg  = bid & 31;
    const int bg  = bid >> 5;
    const int c0  = cg * 32;

    // one-time W slice load, transposed: Wsh[k][j_local]
    {
        const int j  = tid & 31;
        const int kc = tid >> 5;       // 0..7, each 128 k
        const float* wr = Whh + (size_t)(c0 + j) * HH + kc*128;
        #pragma unroll
        for (int i = 0; i < 32; i++) {
            float4 v = *(const float4*)(wr + i*4);
            int k = kc*128 + i*4;
            Wsh[(k+0)*WPAD + j] = v.x;
            Wsh[(k+1)*WPAD + j] = v.y;
            Wsh[(k+2)*WPAD + j] = v.z;
            Wsh[(k+3)*WPAD + j] = v.w;
        }
    }

    const int hb   = tid & 15;
    const int hkc  = tid >> 4;         // 0..15, each 64 k
    const int tile = tid & 7;          // 8 tiles: 2(b) x 4(j)
    const int kg   = tid >> 3;         // 32-way K split
    const int bl0  = (tile >> 2) * 8;  // 0 or 8
    const int jl0  = (tile & 3) * 8;   // 0,8,16,24

    for (int t = 0; t < nsteps; t++) {
        const float* hprev = (t == 0) ? h0 : (y + (size_t)(t-1)*BB*HH);
        __syncthreads();  // W-load done (t=0); red buffer free for reuse

        // load h tile transposed: hsm[k][b_local]
        {
            const float* hr = hprev + (size_t)(bg*16 + hb)*HH + hkc*64;
            #pragma unroll
            for (int i = 0; i < 16; i++) {
                float4 v = *(const float4*)(hr + i*4);
                int k = hkc*64 + i*4;
                hsm[(k+0)*16 + hb] = v.x;
                hsm[(k+1)*16 + hb] = v.y;
                hsm[(k+2)*16 + hb] = v.z;
                hsm[(k+3)*16 + hb] = v.w;
            }
        }
        __syncthreads();

        ull acc2[8][4];
        #pragma unroll
        for (int r = 0; r < 8; r++)
            #pragma unroll
            for (int c = 0; c < 4; c++) acc2[r][c] = 0ull;

        #pragma unroll 2
        for (int i = 0; i < 32; i++) {
            int k = i*32 + kg;
            float4 h0v = *(const float4*)&hsm[k*16 + bl0];
            float4 h1v = *(const float4*)&hsm[k*16 + bl0 + 4];
            ulonglong2 wv0 = *(const ulonglong2*)&Wsh[k*WPAD + jl0];
            ulonglong2 wv1 = *(const ulonglong2*)&Wsh[k*WPAD + jl0 + 4];
            ull wp0 = wv0.x, wp1 = wv0.y, wp2 = wv1.x, wp3 = wv1.y;
            float hv[8] = {h0v.x,h0v.y,h0v.z,h0v.w,h1v.x,h1v.y,h1v.z,h1v.w};
            #pragma unroll
            for (int r = 0; r < 8; r++) {
                ull hd; PACKDUP(hd, hv[r]);
                FFMA2(acc2[r][0], hd, wp0);
                FFMA2(acc2[r][1], hd, wp1);
                FFMA2(acc2[r][2], hd, wp2);
                FFMA2(acc2[r][3], hd, wp3);
            }
        }
        __syncthreads();   // done reading hsm; safe to overwrite as red buffer

        // write partials: pair index = (b)*16 + j/2
        #pragma unroll
        for (int r = 0; r < 8; r++)
            #pragma unroll
            for (int c = 0; c < 4; c++) {
                int p = (bl0 + r) * 16 + (jl0 >> 1) + c;
                red2[kg*RED_ULL_STRIDE + p] = acc2[r][c];
            }
        __syncthreads();

        // reduce 32 partials; each thread owns one output pair p = tid
        {
            ull s0 = red2[tid];
            ull s1 = red2[RED_ULL_STRIDE + tid];
            ull s2 = red2[2*RED_ULL_STRIDE + tid];
            ull s3 = red2[3*RED_ULL_STRIDE + tid];
            #pragma unroll
            for (int g = 4; g < 32; g += 4) {
                ADD2(s0, s0, red2[(g+0)*RED_ULL_STRIDE + tid]);
                ADD2(s1, s1, red2[(g+1)*RED_ULL_STRIDE + tid]);
                ADD2(s2, s2, red2[(g+2)*RED_ULL_STRIDE + tid]);
                ADD2(s3, s3, red2[(g+3)*RED_ULL_STRIDE + tid]);
            }
            ADD2(s0, s0, s1);
            ADD2(s2, s2, s3);
            ADD2(s0, s0, s2);
            unsigned lo, hi;
            UNPACK2(lo, hi, s0);
            int b_local = tid >> 4;
            int j = (tid & 15) * 2;
            int bq = bg*16 + b_local;
            size_t idx = ((size_t)t*BB + bq)*HH + c0 + j;
            float2 xwv = *(const float2*)&xw[idx];
            float2 rv;
            rv.x = tanhf(xwv.x + __uint_as_float(lo));
            rv.y = tanhf(xwv.y + __uint_as_float(hi));
            *(float2*)&y[idx] = rv;
        }

        grid_sync(NB_RNN);
    }
}

// ------------- hidden-state gather ----------------
__global__ void gather_hidden_kernel(float* __restrict__ out_hidden)
{
    int i = blockIdx.x * blockDim.x + threadIdx.x;
    const float* src = (i < BB*HH)
        ? (g_y0 + (size_t)(TT-1)*BB*HH + i)
        : (g_y1 + (size_t)(TT-1)*BB*HH + (i - BB*HH));
    out_hidden[i] = *src;
}

extern "C" void kernel_launch(void* const* d_in, const int* in_sizes, int n_in,
                              void* d_out, int out_size) {
    const float* x     = (const float*)d_in[0];
    const float* h0    = (const float*)d_in[1];
    const float* w_ih0 = (const float*)d_in[2];
    const float* w_hh0 = (const float*)d_in[3];
    const float* b_ih0 = (const float*)d_in[4];
    const float* b_hh0 = (const float*)d_in[5];
    const float* w_ih1 = (const float*)d_in[6];
    const float* w_hh1 = (const float*)d_in[7];
    const float* b_ih1 = (const float*)d_in[8];
    const float* b_hh1 = (const float*)d_in[9];
    const float* w_dec = (const float*)d_in[10];
    const float* b_dec = (const float*)d_in[11];
    float* out = (float*)d_out;

    cudaFuncSetAttribute(rnn_layer_kernel,
                         cudaFuncAttributeMaxDynamicSharedMemorySize, RNN_SMEM);

    float* xw;  cudaGetSymbolAddress((void**)&xw,  g_xw);
    float* y0;  cudaGetSymbolAddress((void**)&y0,  g_y0);
    float* y1;  cudaGetSymbolAddress((void**)&y1,  g_y1);

    dim3 blk(256);

    // 1) layer-0 input projection: xw = x @ w_ih0^T + b_ih0 + b_hh0
    {
        dim3 grid(HH/128, RR/128);
        gemm_bias_kernel<<<grid, blk>>>(x, w_ih0, b_ih0, b_hh0, xw, RR, HH, CC);
    }
    // 2) layer-0 recurrence
    rnn_layer_kernel<<<NB_RNN, blk, RNN_SMEM>>>(xw, h0, w_hh0, y0, TT);
    // 3) layer-1 input projection
    {
        dim3 grid(HH/128, RR/128);
        gemm_bias_kernel<<<grid, blk>>>(y0, w_ih1, b_ih1, b_hh1, xw, RR, HH, HH);
    }
    // 4) layer-1 recurrence
    rnn_layer_kernel<<<NB_RNN, blk, RNN_SMEM>>>(xw, h0 + BB*HH, w_hh1, y1, TT);
    // 5) decoder
    {
        dim3 grid(CC/128, RR/128);
        gemm_bias_kernel<<<grid, blk>>>(y1, w_dec, b_dec, nullptr, out, RR, CC, HH);
    }
    // 6) hidden states appended after decoded
    gather_hidden_kernel<<<(2*BB*HH)/256, blk>>>(out + (size_t)TT*BB*CC);
}